// round 13
// baseline (speedup 1.0000x reference)
#include <cuda_runtime.h>
#include <cuda_fp16.h>
#include <math.h>
#include <stdint.h>

#define DIM 1024
#define DI  1024
#define BAT 8
#define TT  2048
#define MM  (BAT*TT)   /* 16384 rows */
#define EPS 1e-6f
#define NBLK (TT/4)    /* 512 lookahead blocks per batch */

// Scratch (device globals; allocation-free per harness rules)
__device__ __half g_xa[(size_t)MM * DIM];   // fp16 x
__device__ __half g_wi[(size_t)DI * DIM];   // fp16 W_in
__device__ __half g_wc[(size_t)DI * DI];    // fp16 W_cell
__device__ __half g_wo[(size_t)DIM * DI];   // fp16 W_out
__device__ __half g_xp[(size_t)MM * DI];    // silu(x@W_in^T), fp16
__device__ float  g_wx[(size_t)MM * DI];    // xp@W_cell^T + b (fp32)
__device__ __half g_gate[(size_t)MM * DI];  // scan output, fp16
__device__ float  g_qw[(size_t)BAT * NBLK * 12]; // Q0..3, W01,W02,W03,W12,W13,W23,pad2

__device__ __forceinline__ float silu_f(float v) {
    return __fdividef(v, 1.0f + __expf(-v));
}
__device__ __forceinline__ float warp_sum(float v) {
    #pragma unroll
    for (int o = 16; o; o >>= 1) v += __shfl_xor_sync(0xffffffffu, v, o);
    return v;
}
__device__ __forceinline__ float dot4(float4 a, float4 b) {
    return fmaf(a.x, b.x, a.y * b.y) + fmaf(a.z, b.z, a.w * b.w);
}
__device__ __forceinline__ void cpa16(uint32_t dst, const void* src) {
    asm volatile("cp.async.cg.shared.global [%0], [%1], 16;" :: "r"(dst), "l"(src));
}
#define CP_COMMIT() asm volatile("cp.async.commit_group;" ::: "memory")
#define CP_WAIT2()  asm volatile("cp.async.wait_group 2;"  ::: "memory")

__device__ __forceinline__ void ldsm4(uint32_t& r0, uint32_t& r1,
                                      uint32_t& r2, uint32_t& r3, uint32_t addr) {
    asm volatile("ldmatrix.sync.aligned.m8n8.x4.shared.b16 {%0,%1,%2,%3}, [%4];"
                 : "=r"(r0), "=r"(r1), "=r"(r2), "=r"(r3) : "r"(addr));
}

// ---------------------------------------------------------------------------
// fp32 -> fp16 conversion
// ---------------------------------------------------------------------------
__global__ void to_half_kernel(const float* __restrict__ src,
                               __half* __restrict__ dst, int n4)
{
    int i = blockIdx.x * blockDim.x + threadIdx.x;
    if (i >= n4) return;
    float4 v = ((const float4*)src)[i];
    __half2 h01 = __floats2half2_rn(v.x, v.y);
    __half2 h23 = __floats2half2_rn(v.z, v.w);
    uint2 p;
    p.x = *(uint32_t*)&h01;
    p.y = *(uint32_t*)&h23;
    ((uint2*)dst)[i] = p;
}

// ---------------------------------------------------------------------------
// fp16 tensor-core GEMM, warp tile 64x64: block 256x128x32, 8 warps (4Mx2N),
// 1 CTA/SM. ldmatrix + 4-slot cp.async, one barrier per chunk.
// ID: 0 = GEMM1 (silu -> g_xp fp16), 1 = GEMM2 (+bias -> g_wx fp32),
//     2 = GEMM3 (-> Cout fp32)
// ---------------------------------------------------------------------------
#define PITCH_H 40
#define A_ST_H  (256 * PITCH_H)      // A stage: 256 rows
#define B_ST_H  (128 * PITCH_H)      // B stage: 128 rows
#define NSTAGE  4
#define SMEM_BYTES (NSTAGE * (A_ST_H + B_ST_H) * 2)   // 122880 B

template<int ID>
__global__ __launch_bounds__(256, 1)
void gemm_hc(const float* __restrict__ bias, float* __restrict__ Cout)
{
    extern __shared__ __half smh[];   // [A0..A3 B0..B3]

    const int K = 1024, N = 1024;
    const __half* A = (ID == 0) ? g_xa : (ID == 1) ? g_xp : g_gate;
    const __half* W = (ID == 0) ? g_wi : (ID == 1) ? g_wc : g_wo;

    const int tid  = threadIdx.x;
    const int brow = blockIdx.y * 256;
    const int bcol = blockIdx.x * 128;
    const int warp = tid >> 5;
    const int lane = tid & 31;
    const int g    = lane >> 2;
    const int tg   = lane & 3;
    const int warp_m = (warp & 3) * 64;     // 4 warps along M (256)
    const int warp_n = (warp >> 2) * 64;    // 2 warps along N (128)

    const uint32_t smbase = (uint32_t)__cvta_generic_to_shared(smh);
    const uint32_t bbase  = smbase + (uint32_t)(NSTAGE * A_ST_H * 2);

    // cp.async mapping: rows 0..63 (+64*i), 16B unit c0l in 64B row
    const int rA  = tid >> 2;
    const int c0l = tid & 3;

    // ldmatrix lane address components
    const int a_row = warp_m + (lane & 15);
    const int a_kof = (lane >> 4) * 8;
    const int b_row = warp_n + (lane & 7) + ((lane >> 4) & 1) * 8;
    const int b_kof = ((lane >> 3) & 1) * 8;

    float acc[4][8][4];
    #pragma unroll
    for (int i = 0; i < 4; i++)
        #pragma unroll
        for (int j = 0; j < 8; j++)
            #pragma unroll
            for (int r = 0; r < 4; r++) acc[i][j][r] = 0.f;

    auto load_stage = [&](int s, int ch) {
        const int k0 = ch * 32;
        #pragma unroll
        for (int i = 0; i < 4; i++) {
            int r = rA + i * 64;
            cpa16(smbase + (uint32_t)((s * A_ST_H + r * PITCH_H) * 2 + c0l * 16),
                  A + (size_t)(brow + r) * K + k0 + c0l * 8);
        }
        #pragma unroll
        for (int i = 0; i < 2; i++) {
            int r = rA + i * 64;
            cpa16(bbase + (uint32_t)((s * B_ST_H + r * PITCH_H) * 2 + c0l * 16),
                  W + (size_t)(bcol + r) * K + k0 + c0l * 8);
        }
        CP_COMMIT();
    };

    load_stage(0, 0);
    load_stage(1, 1);
    load_stage(2, 2);

    const int NCH = K / 32;   // 32
    for (int ch = 0; ch < NCH; ch++) {
        CP_WAIT2();
        __syncthreads();

        if (ch + 3 < NCH) load_stage((ch + 3) & (NSTAGE - 1), ch + 3);
        else CP_COMMIT();

        const int s = ch & (NSTAGE - 1);
        const uint32_t aT = smbase + (uint32_t)(s * A_ST_H * 2);
        const uint32_t bT = bbase  + (uint32_t)(s * B_ST_H * 2);

        #pragma unroll
        for (int ks = 0; ks < 2; ks++) {
            const int kk = ks * 16;
            uint32_t af[4][4], bf[4][4];
            #pragma unroll
            for (int i = 0; i < 4; i++)
                ldsm4(af[i][0], af[i][1], af[i][2], af[i][3],
                      aT + (uint32_t)(((a_row + i * 16) * PITCH_H + kk + a_kof) * 2));
            #pragma unroll
            for (int j2 = 0; j2 < 4; j2++)
                ldsm4(bf[j2][0], bf[j2][1], bf[j2][2], bf[j2][3],
                      bT + (uint32_t)(((b_row + j2 * 16) * PITCH_H + kk + b_kof) * 2));

            #pragma unroll
            for (int i = 0; i < 4; i++)
                #pragma unroll
                for (int j = 0; j < 8; j++) {
                    const uint32_t bb0 = bf[j >> 1][(j & 1) * 2];
                    const uint32_t bb1 = bf[j >> 1][(j & 1) * 2 + 1];
                    asm volatile(
                        "mma.sync.aligned.m16n8k16.row.col.f32.f16.f16.f32 "
                        "{%0,%1,%2,%3}, {%4,%5,%6,%7}, {%8,%9}, {%0,%1,%2,%3};"
                        : "+f"(acc[i][j][0]), "+f"(acc[i][j][1]),
                          "+f"(acc[i][j][2]), "+f"(acc[i][j][3])
                        : "r"(af[i][0]), "r"(af[i][1]), "r"(af[i][2]), "r"(af[i][3]),
                          "r"(bb0), "r"(bb1));
                }
        }
    }

    // Epilogue
    #pragma unroll
    for (int i = 0; i < 4; i++) {
        int r0 = brow + warp_m + i * 16 + g;
        #pragma unroll
        for (int j = 0; j < 8; j++) {
            int c = bcol + warp_n + j * 8 + tg * 2;
            float e0 = acc[i][j][0], e1 = acc[i][j][1];
            float e2 = acc[i][j][2], e3 = acc[i][j][3];
            if (ID == 0) {
                __half2 lo = __floats2half2_rn(silu_f(e0), silu_f(e1));
                __half2 hi = __floats2half2_rn(silu_f(e2), silu_f(e3));
                *(__half2*)&g_xp[(size_t)r0 * N + c]       = lo;
                *(__half2*)&g_xp[(size_t)(r0 + 8) * N + c] = hi;
            } else if (ID == 1) {
                float b0 = bias[c], b1 = bias[c + 1];
                *(float2*)&g_wx[(size_t)r0 * N + c]       = make_float2(e0 + b0, e1 + b1);
                *(float2*)&g_wx[(size_t)(r0 + 8) * N + c] = make_float2(e2 + b0, e3 + b1);
            } else {
                *(float2*)&Cout[(size_t)r0 * N + c]       = make_float2(e0, e1);
                *(float2*)&Cout[(size_t)(r0 + 8) * N + c] = make_float2(e2, e3);
            }
        }
    }
}

// ---------------------------------------------------------------------------
// Autocorrelation precompute (per batch, per 4-step block):
//   Q_j = sum(wx_j^2), W_ij = sum(wx_i*wx_j), i<j
// ---------------------------------------------------------------------------
__global__ __launch_bounds__(256)
void corr_kernel()
{
    const int blk = blockIdx.x;            // b*NBLK + q
    const int tid = threadIdx.x;
    const int w    = tid >> 5;
    const int lane = tid & 31;
    __shared__ float ws[10][8];

    const size_t rb = (size_t)blk * 4 * DI + tid * 4;
    float4 w0 = *(const float4*)&g_wx[rb];
    float4 w1 = *(const float4*)&g_wx[rb + DI];
    float4 w2 = *(const float4*)&g_wx[rb + 2 * DI];
    float4 w3 = *(const float4*)&g_wx[rb + 3 * DI];

    float p[10];
    p[0] = dot4(w0, w0); p[1] = dot4(w1, w1);
    p[2] = dot4(w2, w2); p[3] = dot4(w3, w3);
    p[4] = dot4(w0, w1); p[5] = dot4(w0, w2); p[6] = dot4(w0, w3);
    p[7] = dot4(w1, w2); p[8] = dot4(w1, w3); p[9] = dot4(w2, w3);

    #pragma unroll
    for (int i = 0; i < 10; i++) p[i] = warp_sum(p[i]);
    if (lane == 0) {
        #pragma unroll
        for (int i = 0; i < 10; i++) ws[i][w] = p[i];
    }
    __syncthreads();
    if (tid < 10) {
        float t = 0.f;
        #pragma unroll
        for (int k = 0; k < 8; k++) t += ws[tid][k];
        g_qw[(size_t)blk * 12 + tid] = t;
    }
}

// ---------------------------------------------------------------------------
// Lookahead-4 scan (R12, unchanged): block loop unrolled x2 for static
// register-array indices; one __syncthreads per 4-step block.
// ---------------------------------------------------------------------------
__global__ __launch_bounds__(256)
void scan_kernel(const float* __restrict__ h0,
                 const float* __restrict__ log_alpha,
                 float* __restrict__ h_final)
{
    const int b    = blockIdx.x;
    const int tid  = threadIdx.x;
    const int w    = tid >> 5;
    const int lane = tid & 31;
    __shared__ __align__(16) float wsum[2][5][8];

    const float alpha = expf(log_alpha[0]);
    const float invD  = 1.0f / DI;

    float4 vv = *(const float4*)&h0[b * DI + tid * 4];
    float v0 = vv.x, v1 = vv.y, v2 = vv.z, v3 = vv.w;

    const size_t base   = (size_t)b * TT * DI + tid * 4;
    const size_t qwbase = (size_t)b * NBLK * 12;

    float4 q[8];
    float4 qw[2][3];
    #pragma unroll
    for (int i = 0; i < 8; i++)
        q[i] = *(const float4*)&g_wx[base + (size_t)i * DI];
    #pragma unroll
    for (int s = 0; s < 2; s++)
        #pragma unroll
        for (int i = 0; i < 3; i++)
            qw[s][i] = *(const float4*)&g_qw[qwbase + s * 12 + i * 4];

    for (int blk2 = 0; blk2 < NBLK; blk2 += 2) {
        #pragma unroll
        for (int par = 0; par < 2; par++) {
            const int blk = blk2 + par;

            float4 w0 = q[par * 4 + 0], w1 = q[par * 4 + 1];
            float4 w2 = q[par * 4 + 2], w3 = q[par * 4 + 3];
            float4 qv0 = qw[par][0], qv1 = qw[par][1], qv2 = qw[par][2];

            if (blk + 2 < NBLK) {
                const size_t nb = base + (size_t)(blk + 2) * 4 * DI;
                q[par * 4 + 0] = *(const float4*)&g_wx[nb];
                q[par * 4 + 1] = *(const float4*)&g_wx[nb + DI];
                q[par * 4 + 2] = *(const float4*)&g_wx[nb + 2 * DI];
                q[par * 4 + 3] = *(const float4*)&g_wx[nb + 3 * DI];
                const size_t nq = qwbase + (size_t)(blk + 2) * 12;
                qw[par][0] = *(const float4*)&g_qw[nq];
                qw[par][1] = *(const float4*)&g_qw[nq + 4];
                qw[par][2] = *(const float4*)&g_qw[nq + 8];
            }

            float4 vf = make_float4(v0, v1, v2, v3);
            float pS = dot4(vf, vf);
            float p0 = dot4(vf, w0), p1 = dot4(vf, w1);
            float p2 = dot4(vf, w2), p3 = dot4(vf, w3);

            #pragma unroll
            for (int o = 16; o; o >>= 1) {
                pS += __shfl_xor_sync(0xffffffffu, pS, o);
                p0 += __shfl_xor_sync(0xffffffffu, p0, o);
                p1 += __shfl_xor_sync(0xffffffffu, p1, o);
                p2 += __shfl_xor_sync(0xffffffffu, p2, o);
                p3 += __shfl_xor_sync(0xffffffffu, p3, o);
            }
            if (lane == 0) {
                wsum[par][0][w] = pS;
                wsum[par][1][w] = p0; wsum[par][2][w] = p1;
                wsum[par][3][w] = p2; wsum[par][4][w] = p3;
            }
            __syncthreads();

            float S0, R0, R1, R2, R3;
            {
                float4 a0 = *(const float4*)&wsum[par][0][0];
                float4 c0 = *(const float4*)&wsum[par][0][4];
                S0 = ((a0.x + a0.y) + (a0.z + a0.w)) + ((c0.x + c0.y) + (c0.z + c0.w));
                float4 a1 = *(const float4*)&wsum[par][1][0];
                float4 c1_ = *(const float4*)&wsum[par][1][4];
                R0 = ((a1.x + a1.y) + (a1.z + a1.w)) + ((c1_.x + c1_.y) + (c1_.z + c1_.w));
                float4 a2 = *(const float4*)&wsum[par][2][0];
                float4 c2_ = *(const float4*)&wsum[par][2][4];
                R1 = ((a2.x + a2.y) + (a2.z + a2.w)) + ((c2_.x + c2_.y) + (c2_.z + c2_.w));
                float4 a3 = *(const float4*)&wsum[par][3][0];
                float4 c3_ = *(const float4*)&wsum[par][3][4];
                R2 = ((a3.x + a3.y) + (a3.z + a3.w)) + ((c3_.x + c3_.y) + (c3_.z + c3_.w));
                float4 a4 = *(const float4*)&wsum[par][4][0];
                float4 c4_ = *(const float4*)&wsum[par][4][4];
                R3 = ((a4.x + a4.y) + (a4.z + a4.w)) + ((c4_.x + c4_.y) + (c4_.z + c4_.w));
            }

            float S = S0, cval = 1.f, cc = 1.f, ic = 1.f;
            float k0, k1, k2, k3, c1, c2, c3, c4;
            {
                float P, m, r;
                k0 = alpha;
                P  = R0;
                S  = S + 2.f * k0 * P + k0 * k0 * qv0.x;
                m  = cc * S * invD + EPS;
                r  = rsqrtf(m);
                cval *= r; cc = cval * cval; ic *= m * r;
                c1 = cval;

                k1 = alpha * ic;
                P  = R1 + k0 * qv1.x;
                S  = S + 2.f * k1 * P + k1 * k1 * qv0.y;
                m  = cc * S * invD + EPS;
                r  = rsqrtf(m);
                cval *= r; cc = cval * cval; ic *= m * r;
                c2 = cval;

                k2 = alpha * ic;
                P  = R2 + k0 * qv1.y + k1 * qv1.w;
                S  = S + 2.f * k2 * P + k2 * k2 * qv0.z;
                m  = cc * S * invD + EPS;
                r  = rsqrtf(m);
                cval *= r; cc = cval * cval; ic *= m * r;
                c3 = cval;

                k3 = alpha * ic;
                P  = R3 + k0 * qv1.z + k1 * qv2.x + k2 * qv2.y;
                S  = S + 2.f * k3 * P + k3 * k3 * qv0.w;
                m  = cc * S * invD + EPS;
                r  = rsqrtf(m);
                cval *= r;
                c4 = cval;
            }

            const size_t ob = base + (size_t)blk * 4 * DI;
            {
                float a0, a1, a2, a3;

                v0 = fmaf(k0, w0.x, v0); v1 = fmaf(k0, w0.y, v1);
                v2 = fmaf(k0, w0.z, v2); v3 = fmaf(k0, w0.w, v3);
                a0 = c1 * v0; a1 = c1 * v1; a2 = c1 * v2; a3 = c1 * v3;
                {
                    float o0 = __fdividef(a0 * a0, 1.0f + __expf(-a0));
                    float o1 = __fdividef(a1 * a1, 1.0f + __expf(-a1));
                    float o2 = __fdividef(a2 * a2, 1.0f + __expf(-a2));
                    float o3 = __fdividef(a3 * a3, 1.0f + __expf(-a3));
                    __half2 pa = __floats2half2_rn(o0, o1);
                    __half2 pb = __floats2half2_rn(o2, o3);
                    uint2 pk; pk.x = *(uint32_t*)&pa; pk.y = *(uint32_t*)&pb;
                    *(uint2*)&g_gate[ob] = pk;
                }

                v0 = fmaf(k1, w1.x, v0); v1 = fmaf(k1, w1.y, v1);
                v2 = fmaf(k1, w1.z, v2); v3 = fmaf(k1, w1.w, v3);
                a0 = c2 * v0; a1 = c2 * v1; a2 = c2 * v2; a3 = c2 * v3;
                {
                    float o0 = __fdividef(a0 * a0, 1.0f + __expf(-a0));
                    float o1 = __fdividef(a1 * a1, 1.0f + __expf(-a1));
                    float o2 = __fdividef(a2 * a2, 1.0f + __expf(-a2));
                    float o3 = __fdividef(a3 * a3, 1.0f + __expf(-a3));
                    __half2 pa = __floats2half2_rn(o0, o1);
                    __half2 pb = __floats2half2_rn(o2, o3);
                    uint2 pk; pk.x = *(uint32_t*)&pa; pk.y = *(uint32_t*)&pb;
                    *(uint2*)&g_gate[ob + DI] = pk;
                }

                v0 = fmaf(k2, w2.x, v0); v1 = fmaf(k2, w2.y, v1);
                v2 = fmaf(k2, w2.z, v2); v3 = fmaf(k2, w2.w, v3);
                a0 = c3 * v0; a1 = c3 * v1; a2 = c3 * v2; a3 = c3 * v3;
                {
                    float o0 = __fdividef(a0 * a0, 1.0f + __expf(-a0));
                    float o1 = __fdividef(a1 * a1, 1.0f + __expf(-a1));
                    float o2 = __fdividef(a2 * a2, 1.0f + __expf(-a2));
                    float o3 = __fdividef(a3 * a3, 1.0f + __expf(-a3));
                    __half2 pa = __floats2half2_rn(o0, o1);
                    __half2 pb = __floats2half2_rn(o2, o3);
                    uint2 pk; pk.x = *(uint32_t*)&pa; pk.y = *(uint32_t*)&pb;
                    *(uint2*)&g_gate[ob + 2 * DI] = pk;
                }

                v0 = fmaf(k3, w3.x, v0); v1 = fmaf(k3, w3.y, v1);
                v2 = fmaf(k3, w3.z, v2); v3 = fmaf(k3, w3.w, v3);
                a0 = c4 * v0; a1 = c4 * v1; a2 = c4 * v2; a3 = c4 * v3;
                {
                    float o0 = __fdividef(a0 * a0, 1.0f + __expf(-a0));
                    float o1 = __fdividef(a1 * a1, 1.0f + __expf(-a1));
                    float o2 = __fdividef(a2 * a2, 1.0f + __expf(-a2));
                    float o3 = __fdividef(a3 * a3, 1.0f + __expf(-a3));
                    __half2 pa = __floats2half2_rn(o0, o1);
                    __half2 pb = __floats2half2_rn(o2, o3);
                    uint2 pk; pk.x = *(uint32_t*)&pa; pk.y = *(uint32_t*)&pb;
                    *(uint2*)&g_gate[ob + 3 * DI] = pk;
                }

                v0 = a0; v1 = a1; v2 = a2; v3 = a3;   // fold c4 into v
            }
        }
    }

    if (h_final)
        *(float4*)&h_final[b * DI + tid * 4] = make_float4(v0, v1, v2, v3);
}

// ---------------------------------------------------------------------------
extern "C" void kernel_launch(void* const* d_in, const int* in_sizes, int n_in,
                              void* d_out, int out_size)
{
    const float* x         = (const float*)d_in[0];
    const float* h0        = (const float*)d_in[1];
    const float* W_in      = (const float*)d_in[2];
    const float* W_cell    = (const float*)d_in[3];
    const float* b_cell    = (const float*)d_in[4];
    const float* log_alpha = (const float*)d_in[5];
    const float* W_out     = (const float*)d_in[6];

    float* y = (float*)d_out;
    const size_t y_elems = (size_t)MM * DIM;
    float* h_final = ((size_t)out_size >= y_elems + (size_t)BAT * DI)
                         ? y + y_elems : nullptr;

    cudaFuncSetAttribute(gemm_hc<0>, cudaFuncAttributeMaxDynamicSharedMemorySize, SMEM_BYTES);
    cudaFuncSetAttribute(gemm_hc<1>, cudaFuncAttributeMaxDynamicSharedMemorySize, SMEM_BYTES);
    cudaFuncSetAttribute(gemm_hc<2>, cudaFuncAttributeMaxDynamicSharedMemorySize, SMEM_BYTES);

    __half *xa, *wi, *wc, *wo;
    cudaGetSymbolAddress((void**)&xa, g_xa);
    cudaGetSymbolAddress((void**)&wi, g_wi);
    cudaGetSymbolAddress((void**)&wc, g_wc);
    cudaGetSymbolAddress((void**)&wo, g_wo);

    // 0) convert mma operands to fp16
    {
        int n4x = (MM * DIM) / 4;
        to_half_kernel<<<(n4x + 255) / 256, 256>>>(x, xa, n4x);
        int n4w = (DI * DIM) / 4;
        to_half_kernel<<<(n4w + 255) / 256, 256>>>(W_in,   wi, n4w);
        to_half_kernel<<<(n4w + 255) / 256, 256>>>(W_cell, wc, n4w);
        to_half_kernel<<<(n4w + 255) / 256, 256>>>(W_out,  wo, n4w);
    }

    dim3 block(256);
    dim3 grid(DI / 128, MM / 256);    // 8 x 64 = 512 CTAs

    // 1) xp = silu(x @ W_in^T)          -> g_xp (fp16)
    gemm_hc<0><<<grid, block, SMEM_BYTES>>>(nullptr, nullptr);
    // 2) Wx = xp @ W_cell^T + b_cell    -> g_wx (fp32)
    gemm_hc<1><<<grid, block, SMEM_BYTES>>>(b_cell, nullptr);
    // 2b) wx autocorrelations
    corr_kernel<<<BAT * NBLK, 256>>>();
    // 3) lookahead-4 scan                -> g_gate (fp16), h_final
    scan_kernel<<<BAT, 256>>>(h0, log_alpha, h_final);
    // 4) y = gate @ W_out^T             -> d_out
    gemm_hc<2><<<dim3(DIM / 128, MM / 256), block, SMEM_BYTES>>>(nullptr, y);
}

// round 14
// speedup vs baseline: 1.0311x; 1.0311x over previous
#include <cuda_runtime.h>
#include <cuda_fp16.h>
#include <math.h>
#include <stdint.h>

#define DIM 1024
#define DI  1024
#define BAT 8
#define TT  2048
#define MM  (BAT*TT)   /* 16384 rows */
#define EPS 1e-6f
#define NBLK (TT/4)    /* 512 lookahead blocks per batch */

// Scratch (device globals; allocation-free per harness rules)
__device__ __half g_xa[(size_t)MM * DIM];   // fp16 x
__device__ __half g_wi[(size_t)DI * DIM];   // fp16 W_in
__device__ __half g_wc[(size_t)DI * DI];    // fp16 W_cell
__device__ __half g_wo[(size_t)DIM * DI];   // fp16 W_out
__device__ __half g_xp[(size_t)MM * DI];    // silu(x@W_in^T), fp16
__device__ float  g_wx[(size_t)MM * DI];    // xp@W_cell^T + b (fp32)
__device__ __half g_gate[(size_t)MM * DI];  // scan output, fp16
__device__ float  g_qw[(size_t)BAT * NBLK * 12]; // Q0..3, W01,W02,W03,W12,W13,W23,pad2

__device__ __forceinline__ float silu_f(float v) {
    return __fdividef(v, 1.0f + __expf(-v));
}
__device__ __forceinline__ float warp_sum(float v) {
    #pragma unroll
    for (int o = 16; o; o >>= 1) v += __shfl_xor_sync(0xffffffffu, v, o);
    return v;
}
__device__ __forceinline__ float dot4(float4 a, float4 b) {
    return fmaf(a.x, b.x, a.y * b.y) + fmaf(a.z, b.z, a.w * b.w);
}
__device__ __forceinline__ void cpa16(uint32_t dst, const void* src) {
    asm volatile("cp.async.cg.shared.global [%0], [%1], 16;" :: "r"(dst), "l"(src));
}
#define CP_COMMIT() asm volatile("cp.async.commit_group;" ::: "memory")
#define CP_WAIT2()  asm volatile("cp.async.wait_group 2;"  ::: "memory")

__device__ __forceinline__ void ldsm4(uint32_t& r0, uint32_t& r1,
                                      uint32_t& r2, uint32_t& r3, uint32_t addr) {
    asm volatile("ldmatrix.sync.aligned.m8n8.x4.shared.b16 {%0,%1,%2,%3}, [%4];"
                 : "=r"(r0), "=r"(r1), "=r"(r2), "=r"(r3) : "r"(addr));
}

// ---------------------------------------------------------------------------
// fp32 -> fp16 conversion
// ---------------------------------------------------------------------------
__global__ void to_half_kernel(const float* __restrict__ src,
                               __half* __restrict__ dst, int n4)
{
    int i = blockIdx.x * blockDim.x + threadIdx.x;
    if (i >= n4) return;
    float4 v = ((const float4*)src)[i];
    __half2 h01 = __floats2half2_rn(v.x, v.y);
    __half2 h23 = __floats2half2_rn(v.z, v.w);
    uint2 p;
    p.x = *(uint32_t*)&h01;
    p.y = *(uint32_t*)&h23;
    ((uint2*)dst)[i] = p;
}

// ---------------------------------------------------------------------------
// fp16 tensor-core GEMM (R12 config): ldmatrix + 4-slot cp.async,
// 1 barrier/chunk, block 128x128x32, 8 warps (2Mx4N), 2 CTAs/SM.
// ID: 0 = GEMM1 (silu -> g_xp fp16)
//     1 = GEMM2 (+bias -> g_wx fp32, FUSED Q/W autocorrelation partials)
//     2 = GEMM3 (-> Cout fp32)
// ---------------------------------------------------------------------------
#define PITCH_H 40
#define TILE_H  (128 * PITCH_H)
#define NSTAGE  4
#define SMEM_BYTES (2 * NSTAGE * TILE_H * 2)   // 81920 B

template<int ID>
__global__ __launch_bounds__(256, 2)
void gemm_hc(const float* __restrict__ bias, float* __restrict__ Cout)
{
    extern __shared__ __half smh[];

    const int K = 1024, N = 1024;
    const __half* A = (ID == 0) ? g_xa : (ID == 1) ? g_xp : g_gate;
    const __half* W = (ID == 0) ? g_wi : (ID == 1) ? g_wc : g_wo;

    const int tid  = threadIdx.x;
    const int brow = blockIdx.y * 128;
    const int bcol = blockIdx.x * 128;
    const int warp = tid >> 5;
    const int lane = tid & 31;
    const int g    = lane >> 2;
    const int tg   = lane & 3;
    const int warp_m = (warp & 1) * 64;
    const int warp_n = (warp >> 1) * 32;

    const uint32_t smbase = (uint32_t)__cvta_generic_to_shared(smh);

    const int r0l = tid >> 2;
    const int c0l = tid & 3;

    const int a_row = warp_m + (lane & 15);
    const int a_kof = (lane >> 4) * 8;
    const int b_row = warp_n + (lane & 7) + ((lane >> 4) & 1) * 8;
    const int b_kof = ((lane >> 3) & 1) * 8;

    float acc[4][4][4];
    #pragma unroll
    for (int i = 0; i < 4; i++)
        #pragma unroll
        for (int j = 0; j < 4; j++)
            #pragma unroll
            for (int r = 0; r < 4; r++) acc[i][j][r] = 0.f;

    auto load_stage = [&](int s, int ch) {
        const int k0 = ch * 32;
        #pragma unroll
        for (int i = 0; i < 2; i++) {
            int r = r0l + i * 64;
            cpa16(smbase + (uint32_t)(((s * TILE_H) + r * PITCH_H) * 2 + c0l * 16),
                  A + (size_t)(brow + r) * K + k0 + c0l * 8);
            cpa16(smbase + (uint32_t)((((NSTAGE + s) * TILE_H) + r * PITCH_H) * 2 + c0l * 16),
                  W + (size_t)(bcol + r) * K + k0 + c0l * 8);
        }
        CP_COMMIT();
    };

    load_stage(0, 0);
    load_stage(1, 1);
    load_stage(2, 2);

    const int NCH = K / 32;
    for (int ch = 0; ch < NCH; ch++) {
        CP_WAIT2();
        __syncthreads();

        if (ch + 3 < NCH) load_stage((ch + 3) & (NSTAGE - 1), ch + 3);
        else CP_COMMIT();

        const int s = ch & (NSTAGE - 1);
        const uint32_t aT = smbase + (uint32_t)(s * TILE_H * 2);
        const uint32_t bT = smbase + (uint32_t)((NSTAGE + s) * TILE_H * 2);

        #pragma unroll
        for (int ks = 0; ks < 2; ks++) {
            const int kk = ks * 16;
            uint32_t af[4][4], bf[2][4];
            #pragma unroll
            for (int i = 0; i < 4; i++)
                ldsm4(af[i][0], af[i][1], af[i][2], af[i][3],
                      aT + (uint32_t)(((a_row + i * 16) * PITCH_H + kk + a_kof) * 2));
            #pragma unroll
            for (int j2 = 0; j2 < 2; j2++)
                ldsm4(bf[j2][0], bf[j2][1], bf[j2][2], bf[j2][3],
                      bT + (uint32_t)(((b_row + j2 * 16) * PITCH_H + kk + b_kof) * 2));

            #pragma unroll
            for (int i = 0; i < 4; i++)
                #pragma unroll
                for (int j = 0; j < 4; j++) {
                    const uint32_t bb0 = bf[j >> 1][(j & 1) * 2];
                    const uint32_t bb1 = bf[j >> 1][(j & 1) * 2 + 1];
                    asm volatile(
                        "mma.sync.aligned.m16n8k16.row.col.f32.f16.f16.f32 "
                        "{%0,%1,%2,%3}, {%4,%5,%6,%7}, {%8,%9}, {%0,%1,%2,%3};"
                        : "+f"(acc[i][j][0]), "+f"(acc[i][j][1]),
                          "+f"(acc[i][j][2]), "+f"(acc[i][j][3])
                        : "r"(af[i][0]), "r"(af[i][1]), "r"(af[i][2]), "r"(af[i][3]),
                          "r"(bb0), "r"(bb1));
                }
        }
    }

    // ---------------- Epilogue ----------------
    if (ID == 1) {
        // GEMM2: store wx AND accumulate Q/W autocorrelation partials.
        // Row of thread: r0 = brow+warp_m+i*16+g and r0+8. Block-local pos
        // a = g&3 (warp_m, i*16, brow all multiples of 4). Rows g and g^d
        // (d=1..3) are in the same 4-block; partner via shfl.xor lane^(4d)
        // (keeps tg and g-bit2). Pair dedup: thread with a < (a^d) owns it.
        #pragma unroll
        for (int i = 0; i < 4; i++) {
            int r0 = brow + warp_m + i * 16 + g;
            float qA = 0.f, qB = 0.f;
            float wA1 = 0.f, wA2 = 0.f, wA3 = 0.f;
            float wB1 = 0.f, wB2 = 0.f, wB3 = 0.f;
            #pragma unroll
            for (int j = 0; j < 4; j++) {
                int c = bcol + warp_n + j * 8 + tg * 2;
                float b0 = bias[c], b1 = bias[c + 1];
                float e0 = acc[i][j][0] + b0, e1 = acc[i][j][1] + b1;
                float e2 = acc[i][j][2] + b0, e3 = acc[i][j][3] + b1;
                *(float2*)&g_wx[(size_t)r0 * N + c]       = make_float2(e0, e1);
                *(float2*)&g_wx[(size_t)(r0 + 8) * N + c] = make_float2(e2, e3);

                qA = fmaf(e0, e0, qA); qA = fmaf(e1, e1, qA);
                qB = fmaf(e2, e2, qB); qB = fmaf(e3, e3, qB);

                float f0, f1, f2, f3;
                f0 = __shfl_xor_sync(0xffffffffu, e0, 4);
                f1 = __shfl_xor_sync(0xffffffffu, e1, 4);
                f2 = __shfl_xor_sync(0xffffffffu, e2, 4);
                f3 = __shfl_xor_sync(0xffffffffu, e3, 4);
                wA1 = fmaf(e0, f0, wA1); wA1 = fmaf(e1, f1, wA1);
                wB1 = fmaf(e2, f2, wB1); wB1 = fmaf(e3, f3, wB1);

                f0 = __shfl_xor_sync(0xffffffffu, e0, 8);
                f1 = __shfl_xor_sync(0xffffffffu, e1, 8);
                f2 = __shfl_xor_sync(0xffffffffu, e2, 8);
                f3 = __shfl_xor_sync(0xffffffffu, e3, 8);
                wA2 = fmaf(e0, f0, wA2); wA2 = fmaf(e1, f1, wA2);
                wB2 = fmaf(e2, f2, wB2); wB2 = fmaf(e3, f3, wB2);

                f0 = __shfl_xor_sync(0xffffffffu, e0, 12);
                f1 = __shfl_xor_sync(0xffffffffu, e1, 12);
                f2 = __shfl_xor_sync(0xffffffffu, e2, 12);
                f3 = __shfl_xor_sync(0xffffffffu, e3, 12);
                wA3 = fmaf(e0, f0, wA3); wA3 = fmaf(e1, f1, wA3);
                wB3 = fmaf(e2, f2, wB3); wB3 = fmaf(e3, f3, wB3);
            }
            // reduce over tg (lanes xor 1, 2)
            qA  += __shfl_xor_sync(0xffffffffu, qA, 1);  qA  += __shfl_xor_sync(0xffffffffu, qA, 2);
            qB  += __shfl_xor_sync(0xffffffffu, qB, 1);  qB  += __shfl_xor_sync(0xffffffffu, qB, 2);
            wA1 += __shfl_xor_sync(0xffffffffu, wA1, 1); wA1 += __shfl_xor_sync(0xffffffffu, wA1, 2);
            wB1 += __shfl_xor_sync(0xffffffffu, wB1, 1); wB1 += __shfl_xor_sync(0xffffffffu, wB1, 2);
            wA2 += __shfl_xor_sync(0xffffffffu, wA2, 1); wA2 += __shfl_xor_sync(0xffffffffu, wA2, 2);
            wB2 += __shfl_xor_sync(0xffffffffu, wB2, 1); wB2 += __shfl_xor_sync(0xffffffffu, wB2, 2);
            wA3 += __shfl_xor_sync(0xffffffffu, wA3, 1); wA3 += __shfl_xor_sync(0xffffffffu, wA3, 2);
            wB3 += __shfl_xor_sync(0xffffffffu, wB3, 1); wB3 += __shfl_xor_sync(0xffffffffu, wB3, 2);

            if (tg == 0) {
                const int a = g & 3;
                float* qwA = &g_qw[(size_t)(r0 >> 2) * 12];
                float* qwB = qwA + 24;   // row r0+8 -> block +2
                atomicAdd(&qwA[a], qA);
                atomicAdd(&qwB[a], qB);
                if (a == 0) {
                    atomicAdd(&qwA[4], wA1); atomicAdd(&qwB[4], wB1);  // W01
                    atomicAdd(&qwA[5], wA2); atomicAdd(&qwB[5], wB2);  // W02
                    atomicAdd(&qwA[6], wA3); atomicAdd(&qwB[6], wB3);  // W03
                } else if (a == 1) {
                    atomicAdd(&qwA[8], wA2); atomicAdd(&qwB[8], wB2);  // W13 (d=2)
                    atomicAdd(&qwA[7], wA3); atomicAdd(&qwB[7], wB3);  // W12 (d=3)
                } else if (a == 2) {
                    atomicAdd(&qwA[9], wA1); atomicAdd(&qwB[9], wB1);  // W23 (d=1)
                }
            }
        }
    } else {
        #pragma unroll
        for (int i = 0; i < 4; i++) {
            int r0 = brow + warp_m + i * 16 + g;
            #pragma unroll
            for (int j = 0; j < 4; j++) {
                int c = bcol + warp_n + j * 8 + tg * 2;
                float e0 = acc[i][j][0], e1 = acc[i][j][1];
                float e2 = acc[i][j][2], e3 = acc[i][j][3];
                if (ID == 0) {
                    __half2 lo = __floats2half2_rn(silu_f(e0), silu_f(e1));
                    __half2 hi = __floats2half2_rn(silu_f(e2), silu_f(e3));
                    *(__half2*)&g_xp[(size_t)r0 * N + c]       = lo;
                    *(__half2*)&g_xp[(size_t)(r0 + 8) * N + c] = hi;
                } else {
                    *(float2*)&Cout[(size_t)r0 * N + c]       = make_float2(e0, e1);
                    *(float2*)&Cout[(size_t)(r0 + 8) * N + c] = make_float2(e2, e3);
                }
            }
        }
    }
}

// ---------------------------------------------------------------------------
// Lookahead-4 scan (R12, unchanged): block loop unrolled x2 for static
// register-array indices; one __syncthreads per 4-step block.
// ---------------------------------------------------------------------------
__global__ __launch_bounds__(256)
void scan_kernel(const float* __restrict__ h0,
                 const float* __restrict__ log_alpha,
                 float* __restrict__ h_final)
{
    const int b    = blockIdx.x;
    const int tid  = threadIdx.x;
    const int w    = tid >> 5;
    const int lane = tid & 31;
    __shared__ __align__(16) float wsum[2][5][8];

    const float alpha = expf(log_alpha[0]);
    const float invD  = 1.0f / DI;

    float4 vv = *(const float4*)&h0[b * DI + tid * 4];
    float v0 = vv.x, v1 = vv.y, v2 = vv.z, v3 = vv.w;

    const size_t base   = (size_t)b * TT * DI + tid * 4;
    const size_t qwbase = (size_t)b * NBLK * 12;

    float4 q[8];
    float4 qw[2][3];
    #pragma unroll
    for (int i = 0; i < 8; i++)
        q[i] = *(const float4*)&g_wx[base + (size_t)i * DI];
    #pragma unroll
    for (int s = 0; s < 2; s++)
        #pragma unroll
        for (int i = 0; i < 3; i++)
            qw[s][i] = *(const float4*)&g_qw[qwbase + s * 12 + i * 4];

    for (int blk2 = 0; blk2 < NBLK; blk2 += 2) {
        #pragma unroll
        for (int par = 0; par < 2; par++) {
            const int blk = blk2 + par;

            float4 w0 = q[par * 4 + 0], w1 = q[par * 4 + 1];
            float4 w2 = q[par * 4 + 2], w3 = q[par * 4 + 3];
            float4 qv0 = qw[par][0], qv1 = qw[par][1], qv2 = qw[par][2];

            if (blk + 2 < NBLK) {
                const size_t nb = base + (size_t)(blk + 2) * 4 * DI;
                q[par * 4 + 0] = *(const float4*)&g_wx[nb];
                q[par * 4 + 1] = *(const float4*)&g_wx[nb + DI];
                q[par * 4 + 2] = *(const float4*)&g_wx[nb + 2 * DI];
                q[par * 4 + 3] = *(const float4*)&g_wx[nb + 3 * DI];
                const size_t nq = qwbase + (size_t)(blk + 2) * 12;
                qw[par][0] = *(const float4*)&g_qw[nq];
                qw[par][1] = *(const float4*)&g_qw[nq + 4];
                qw[par][2] = *(const float4*)&g_qw[nq + 8];
            }

            float4 vf = make_float4(v0, v1, v2, v3);
            float pS = dot4(vf, vf);
            float p0 = dot4(vf, w0), p1 = dot4(vf, w1);
            float p2 = dot4(vf, w2), p3 = dot4(vf, w3);

            #pragma unroll
            for (int o = 16; o; o >>= 1) {
                pS += __shfl_xor_sync(0xffffffffu, pS, o);
                p0 += __shfl_xor_sync(0xffffffffu, p0, o);
                p1 += __shfl_xor_sync(0xffffffffu, p1, o);
                p2 += __shfl_xor_sync(0xffffffffu, p2, o);
                p3 += __shfl_xor_sync(0xffffffffu, p3, o);
            }
            if (lane == 0) {
                wsum[par][0][w] = pS;
                wsum[par][1][w] = p0; wsum[par][2][w] = p1;
                wsum[par][3][w] = p2; wsum[par][4][w] = p3;
            }
            __syncthreads();

            float S0, R0, R1, R2, R3;
            {
                float4 a0 = *(const float4*)&wsum[par][0][0];
                float4 c0 = *(const float4*)&wsum[par][0][4];
                S0 = ((a0.x + a0.y) + (a0.z + a0.w)) + ((c0.x + c0.y) + (c0.z + c0.w));
                float4 a1 = *(const float4*)&wsum[par][1][0];
                float4 c1_ = *(const float4*)&wsum[par][1][4];
                R0 = ((a1.x + a1.y) + (a1.z + a1.w)) + ((c1_.x + c1_.y) + (c1_.z + c1_.w));
                float4 a2 = *(const float4*)&wsum[par][2][0];
                float4 c2_ = *(const float4*)&wsum[par][2][4];
                R1 = ((a2.x + a2.y) + (a2.z + a2.w)) + ((c2_.x + c2_.y) + (c2_.z + c2_.w));
                float4 a3 = *(const float4*)&wsum[par][3][0];
                float4 c3_ = *(const float4*)&wsum[par][3][4];
                R2 = ((a3.x + a3.y) + (a3.z + a3.w)) + ((c3_.x + c3_.y) + (c3_.z + c3_.w));
                float4 a4 = *(const float4*)&wsum[par][4][0];
                float4 c4_ = *(const float4*)&wsum[par][4][4];
                R3 = ((a4.x + a4.y) + (a4.z + a4.w)) + ((c4_.x + c4_.y) + (c4_.z + c4_.w));
            }

            float S = S0, cval = 1.f, cc = 1.f, ic = 1.f;
            float k0, k1, k2, k3, c1, c2, c3, c4;
            {
                float P, m, r;
                k0 = alpha;
                P  = R0;
                S  = S + 2.f * k0 * P + k0 * k0 * qv0.x;
                m  = cc * S * invD + EPS;
                r  = rsqrtf(m);
                cval *= r; cc = cval * cval; ic *= m * r;
                c1 = cval;

                k1 = alpha * ic;
                P  = R1 + k0 * qv1.x;
                S  = S + 2.f * k1 * P + k1 * k1 * qv0.y;
                m  = cc * S * invD + EPS;
                r  = rsqrtf(m);
                cval *= r; cc = cval * cval; ic *= m * r;
                c2 = cval;

                k2 = alpha * ic;
                P  = R2 + k0 * qv1.y + k1 * qv1.w;
                S  = S + 2.f * k2 * P + k2 * k2 * qv0.z;
                m  = cc * S * invD + EPS;
                r  = rsqrtf(m);
                cval *= r; cc = cval * cval; ic *= m * r;
                c3 = cval;

                k3 = alpha * ic;
                P  = R3 + k0 * qv1.z + k1 * qv2.x + k2 * qv2.y;
                S  = S + 2.f * k3 * P + k3 * k3 * qv0.w;
                m  = cc * S * invD + EPS;
                r  = rsqrtf(m);
                cval *= r;
                c4 = cval;
            }

            const size_t ob = base + (size_t)blk * 4 * DI;
            {
                float a0, a1, a2, a3;

                v0 = fmaf(k0, w0.x, v0); v1 = fmaf(k0, w0.y, v1);
                v2 = fmaf(k0, w0.z, v2); v3 = fmaf(k0, w0.w, v3);
                a0 = c1 * v0; a1 = c1 * v1; a2 = c1 * v2; a3 = c1 * v3;
                {
                    float o0 = __fdividef(a0 * a0, 1.0f + __expf(-a0));
                    float o1 = __fdividef(a1 * a1, 1.0f + __expf(-a1));
                    float o2 = __fdividef(a2 * a2, 1.0f + __expf(-a2));
                    float o3 = __fdividef(a3 * a3, 1.0f + __expf(-a3));
                    __half2 pa = __floats2half2_rn(o0, o1);
                    __half2 pb = __floats2half2_rn(o2, o3);
                    uint2 pk; pk.x = *(uint32_t*)&pa; pk.y = *(uint32_t*)&pb;
                    *(uint2*)&g_gate[ob] = pk;
                }

                v0 = fmaf(k1, w1.x, v0); v1 = fmaf(k1, w1.y, v1);
                v2 = fmaf(k1, w1.z, v2); v3 = fmaf(k1, w1.w, v3);
                a0 = c2 * v0; a1 = c2 * v1; a2 = c2 * v2; a3 = c2 * v3;
                {
                    float o0 = __fdividef(a0 * a0, 1.0f + __expf(-a0));
                    float o1 = __fdividef(a1 * a1, 1.0f + __expf(-a1));
                    float o2 = __fdividef(a2 * a2, 1.0f + __expf(-a2));
                    float o3 = __fdividef(a3 * a3, 1.0f + __expf(-a3));
                    __half2 pa = __floats2half2_rn(o0, o1);
                    __half2 pb = __floats2half2_rn(o2, o3);
                    uint2 pk; pk.x = *(uint32_t*)&pa; pk.y = *(uint32_t*)&pb;
                    *(uint2*)&g_gate[ob + DI] = pk;
                }

                v0 = fmaf(k2, w2.x, v0); v1 = fmaf(k2, w2.y, v1);
                v2 = fmaf(k2, w2.z, v2); v3 = fmaf(k2, w2.w, v3);
                a0 = c3 * v0; a1 = c3 * v1; a2 = c3 * v2; a3 = c3 * v3;
                {
                    float o0 = __fdividef(a0 * a0, 1.0f + __expf(-a0));
                    float o1 = __fdividef(a1 * a1, 1.0f + __expf(-a1));
                    float o2 = __fdividef(a2 * a2, 1.0f + __expf(-a2));
                    float o3 = __fdividef(a3 * a3, 1.0f + __expf(-a3));
                    __half2 pa = __floats2half2_rn(o0, o1);
                    __half2 pb = __floats2half2_rn(o2, o3);
                    uint2 pk; pk.x = *(uint32_t*)&pa; pk.y = *(uint32_t*)&pb;
                    *(uint2*)&g_gate[ob + 2 * DI] = pk;
                }

                v0 = fmaf(k3, w3.x, v0); v1 = fmaf(k3, w3.y, v1);
                v2 = fmaf(k3, w3.z, v2); v3 = fmaf(k3, w3.w, v3);
                a0 = c4 * v0; a1 = c4 * v1; a2 = c4 * v2; a3 = c4 * v3;
                {
                    float o0 = __fdividef(a0 * a0, 1.0f + __expf(-a0));
                    float o1 = __fdividef(a1 * a1, 1.0f + __expf(-a1));
                    float o2 = __fdividef(a2 * a2, 1.0f + __expf(-a2));
                    float o3 = __fdividef(a3 * a3, 1.0f + __expf(-a3));
                    __half2 pa = __floats2half2_rn(o0, o1);
                    __half2 pb = __floats2half2_rn(o2, o3);
                    uint2 pk; pk.x = *(uint32_t*)&pa; pk.y = *(uint32_t*)&pb;
                    *(uint2*)&g_gate[ob + 3 * DI] = pk;
                }

                v0 = a0; v1 = a1; v2 = a2; v3 = a3;   // fold c4 into v
            }
        }
    }

    if (h_final)
        *(float4*)&h_final[b * DI + tid * 4] = make_float4(v0, v1, v2, v3);
}

// ---------------------------------------------------------------------------
extern "C" void kernel_launch(void* const* d_in, const int* in_sizes, int n_in,
                              void* d_out, int out_size)
{
    const float* x         = (const float*)d_in[0];
    const float* h0        = (const float*)d_in[1];
    const float* W_in      = (const float*)d_in[2];
    const float* W_cell    = (const float*)d_in[3];
    const float* b_cell    = (const float*)d_in[4];
    const float* log_alpha = (const float*)d_in[5];
    const float* W_out     = (const float*)d_in[6];

    float* y = (float*)d_out;
    const size_t y_elems = (size_t)MM * DIM;
    float* h_final = ((size_t)out_size >= y_elems + (size_t)BAT * DI)
                         ? y + y_elems : nullptr;

    cudaFuncSetAttribute(gemm_hc<0>, cudaFuncAttributeMaxDynamicSharedMemorySize, SMEM_BYTES);
    cudaFuncSetAttribute(gemm_hc<1>, cudaFuncAttributeMaxDynamicSharedMemorySize, SMEM_BYTES);
    cudaFuncSetAttribute(gemm_hc<2>, cudaFuncAttributeMaxDynamicSharedMemorySize, SMEM_BYTES);

    __half *xa, *wi, *wc, *wo;
    float  *qwp;
    cudaGetSymbolAddress((void**)&xa,  g_xa);
    cudaGetSymbolAddress((void**)&wi,  g_wi);
    cudaGetSymbolAddress((void**)&wc,  g_wc);
    cudaGetSymbolAddress((void**)&wo,  g_wo);
    cudaGetSymbolAddress((void**)&qwp, g_qw);

    // 0) convert mma operands to fp16
    {
        int n4x = (MM * DIM) / 4;
        to_half_kernel<<<(n4x + 255) / 256, 256>>>(x, xa, n4x);
        int n4w = (DI * DIM) / 4;
        to_half_kernel<<<(n4w + 255) / 256, 256>>>(W_in,   wi, n4w);
        to_half_kernel<<<(n4w + 255) / 256, 256>>>(W_cell, wc, n4w);
        to_half_kernel<<<(n4w + 255) / 256, 256>>>(W_out,  wo, n4w);
    }

    dim3 block(256);
    dim3 grid(DI / 128, MM / 128);

    // 1) xp = silu(x @ W_in^T)          -> g_xp (fp16)
    gemm_hc<0><<<grid, block, SMEM_BYTES>>>(nullptr, nullptr);
    // 1b) zero the Q/W accumulators (capture-legal async memset)
    cudaMemsetAsync(qwp, 0, (size_t)BAT * NBLK * 12 * sizeof(float), 0);
    // 2) Wx = xp @ W_cell^T + b_cell    -> g_wx (fp32) + fused Q/W partials
    gemm_hc<1><<<grid, block, SMEM_BYTES>>>(b_cell, nullptr);
    // 3) lookahead-4 scan                -> g_gate (fp16), h_final
    scan_kernel<<<BAT, 256>>>(h0, log_alpha, h_final);
    // 4) y = gate @ W_out^T             -> d_out
    gemm_hc<2><<<dim3(DIM / 128, MM / 128), block, SMEM_BYTES>>>(nullptr, y);
}

// round 17
// speedup vs baseline: 1.1692x; 1.1339x over previous
#include <cuda_runtime.h>
#include <cuda_fp16.h>
#include <math.h>
#include <stdint.h>

#define DIM 1024
#define DI  1024
#define BAT 8
#define TT  2048
#define MM  (BAT*TT)   /* 16384 rows */
#define EPS 1e-6f
#define NBLK (TT/4)    /* 512 lookahead blocks per batch */

// Scratch (device globals; allocation-free per harness rules)
__device__ __half g_xa[(size_t)MM * DIM];   // fp16 x
__device__ __half g_wi[(size_t)DI * DIM];   // fp16 W_in
__device__ __half g_wc[(size_t)DI * DI];    // fp16 W_cell
__device__ __half g_wo[(size_t)DIM * DI];   // fp16 W_out
__device__ __half g_xp[(size_t)MM * DI];    // silu(x@W_in^T), fp16
__device__ __half g_wx[(size_t)MM * DI];    // xp@W_cell^T + b, fp16
__device__ __half g_gate[(size_t)MM * DI];  // scan output, fp16
__device__ float  g_qw[(size_t)BAT * NBLK * 12]; // Q0..3, W01,W02,W03,W12,W13,W23,pad2

__device__ __forceinline__ float silu_f(float v) {
    return __fdividef(v, 1.0f + __expf(-v));
}
__device__ __forceinline__ float warp_sum(float v) {
    #pragma unroll
    for (int o = 16; o; o >>= 1) v += __shfl_xor_sync(0xffffffffu, v, o);
    return v;
}
__device__ __forceinline__ float dot4(float4 a, float4 b) {
    return fmaf(a.x, b.x, a.y * b.y) + fmaf(a.z, b.z, a.w * b.w);
}
__device__ __forceinline__ float4 h2f4(uint2 p) {
    __half2 a = *(__half2*)&p.x;
    __half2 b = *(__half2*)&p.y;
    float2 fa = __half22float2(a), fb = __half22float2(b);
    return make_float4(fa.x, fa.y, fb.x, fb.y);
}
__device__ __forceinline__ void cpa16(uint32_t dst, const void* src) {
    asm volatile("cp.async.cg.shared.global [%0], [%1], 16;" :: "r"(dst), "l"(src));
}
#define CP_COMMIT() asm volatile("cp.async.commit_group;" ::: "memory")
#define CP_WAIT2()  asm volatile("cp.async.wait_group 2;"  ::: "memory")

__device__ __forceinline__ void ldsm4(uint32_t& r0, uint32_t& r1,
                                      uint32_t& r2, uint32_t& r3, uint32_t addr) {
    asm volatile("ldmatrix.sync.aligned.m8n8.x4.shared.b16 {%0,%1,%2,%3}, [%4];"
                 : "=r"(r0), "=r"(r1), "=r"(r2), "=r"(r3) : "r"(addr));
}

// ---------------------------------------------------------------------------
// fp32 -> fp16 conversion
// ---------------------------------------------------------------------------
__global__ void to_half_kernel(const float* __restrict__ src,
                               __half* __restrict__ dst, int n4)
{
    int i = blockIdx.x * blockDim.x + threadIdx.x;
    if (i >= n4) return;
    float4 v = ((const float4*)src)[i];
    __half2 h01 = __floats2half2_rn(v.x, v.y);
    __half2 h23 = __floats2half2_rn(v.z, v.w);
    uint2 p;
    p.x = *(uint32_t*)&h01;
    p.y = *(uint32_t*)&h23;
    ((uint2*)dst)[i] = p;
}

// ---------------------------------------------------------------------------
// fp16 tensor-core GEMM (R12 config): ldmatrix + 4-slot cp.async,
// 1 barrier/chunk, block 128x128x32, 8 warps (2Mx4N), 2 CTAs/SM.
// ID: 0 = GEMM1 (silu -> g_xp fp16), 1 = GEMM2 (+bias -> g_wx fp16),
//     2 = GEMM3 (-> Cout fp32)
// ---------------------------------------------------------------------------
#define PITCH_H 40
#define TILE_H  (128 * PITCH_H)
#define NSTAGE  4
#define SMEM_BYTES (2 * NSTAGE * TILE_H * 2)   // 81920 B

template<int ID>
__global__ __launch_bounds__(256, 2)
void gemm_hc(const float* __restrict__ bias, float* __restrict__ Cout)
{
    extern __shared__ __half smh[];

    const int K = 1024, N = 1024;
    const __half* A = (ID == 0) ? g_xa : (ID == 1) ? g_xp : g_gate;
    const __half* W = (ID == 0) ? g_wi : (ID == 1) ? g_wc : g_wo;

    const int tid  = threadIdx.x;
    const int brow = blockIdx.y * 128;
    const int bcol = blockIdx.x * 128;
    const int warp = tid >> 5;
    const int lane = tid & 31;
    const int g    = lane >> 2;
    const int tg   = lane & 3;
    const int warp_m = (warp & 1) * 64;
    const int warp_n = (warp >> 1) * 32;

    const uint32_t smbase = (uint32_t)__cvta_generic_to_shared(smh);

    const int r0l = tid >> 2;
    const int c0l = tid & 3;

    const int a_row = warp_m + (lane & 15);
    const int a_kof = (lane >> 4) * 8;
    const int b_row = warp_n + (lane & 7) + ((lane >> 4) & 1) * 8;
    const int b_kof = ((lane >> 3) & 1) * 8;

    float acc[4][4][4];
    #pragma unroll
    for (int i = 0; i < 4; i++)
        #pragma unroll
        for (int j = 0; j < 4; j++)
            #pragma unroll
            for (int r = 0; r < 4; r++) acc[i][j][r] = 0.f;

    auto load_stage = [&](int s, int ch) {
        const int k0 = ch * 32;
        #pragma unroll
        for (int i = 0; i < 2; i++) {
            int r = r0l + i * 64;
            cpa16(smbase + (uint32_t)(((s * TILE_H) + r * PITCH_H) * 2 + c0l * 16),
                  A + (size_t)(brow + r) * K + k0 + c0l * 8);
            cpa16(smbase + (uint32_t)((((NSTAGE + s) * TILE_H) + r * PITCH_H) * 2 + c0l * 16),
                  W + (size_t)(bcol + r) * K + k0 + c0l * 8);
        }
        CP_COMMIT();
    };

    load_stage(0, 0);
    load_stage(1, 1);
    load_stage(2, 2);

    const int NCH = K / 32;
    for (int ch = 0; ch < NCH; ch++) {
        CP_WAIT2();
        __syncthreads();

        if (ch + 3 < NCH) load_stage((ch + 3) & (NSTAGE - 1), ch + 3);
        else CP_COMMIT();

        const int s = ch & (NSTAGE - 1);
        const uint32_t aT = smbase + (uint32_t)(s * TILE_H * 2);
        const uint32_t bT = smbase + (uint32_t)((NSTAGE + s) * TILE_H * 2);

        #pragma unroll
        for (int ks = 0; ks < 2; ks++) {
            const int kk = ks * 16;
            uint32_t af[4][4], bf[2][4];
            #pragma unroll
            for (int i = 0; i < 4; i++)
                ldsm4(af[i][0], af[i][1], af[i][2], af[i][3],
                      aT + (uint32_t)(((a_row + i * 16) * PITCH_H + kk + a_kof) * 2));
            #pragma unroll
            for (int j2 = 0; j2 < 2; j2++)
                ldsm4(bf[j2][0], bf[j2][1], bf[j2][2], bf[j2][3],
                      bT + (uint32_t)(((b_row + j2 * 16) * PITCH_H + kk + b_kof) * 2));

            #pragma unroll
            for (int i = 0; i < 4; i++)
                #pragma unroll
                for (int j = 0; j < 4; j++) {
                    const uint32_t bb0 = bf[j >> 1][(j & 1) * 2];
                    const uint32_t bb1 = bf[j >> 1][(j & 1) * 2 + 1];
                    asm volatile(
                        "mma.sync.aligned.m16n8k16.row.col.f32.f16.f16.f32 "
                        "{%0,%1,%2,%3}, {%4,%5,%6,%7}, {%8,%9}, {%0,%1,%2,%3};"
                        : "+f"(acc[i][j][0]), "+f"(acc[i][j][1]),
                          "+f"(acc[i][j][2]), "+f"(acc[i][j][3])
                        : "r"(af[i][0]), "r"(af[i][1]), "r"(af[i][2]), "r"(af[i][3]),
                          "r"(bb0), "r"(bb1));
                }
        }
    }

    #pragma unroll
    for (int i = 0; i < 4; i++) {
        int r0 = brow + warp_m + i * 16 + g;
        #pragma unroll
        for (int j = 0; j < 4; j++) {
            int c = bcol + warp_n + j * 8 + tg * 2;
            float e0 = acc[i][j][0], e1 = acc[i][j][1];
            float e2 = acc[i][j][2], e3 = acc[i][j][3];
            if (ID == 0) {
                __half2 lo = __floats2half2_rn(silu_f(e0), silu_f(e1));
                __half2 hi = __floats2half2_rn(silu_f(e2), silu_f(e3));
                *(__half2*)&g_xp[(size_t)r0 * N + c]       = lo;
                *(__half2*)&g_xp[(size_t)(r0 + 8) * N + c] = hi;
            } else if (ID == 1) {
                float b0 = bias[c], b1 = bias[c + 1];
                __half2 lo = __floats2half2_rn(e0 + b0, e1 + b1);
                __half2 hi = __floats2half2_rn(e2 + b0, e3 + b1);
                *(__half2*)&g_wx[(size_t)r0 * N + c]       = lo;
                *(__half2*)&g_wx[(size_t)(r0 + 8) * N + c] = hi;
            } else {
                *(float2*)&Cout[(size_t)r0 * N + c]       = make_float2(e0, e1);
                *(float2*)&Cout[(size_t)(r0 + 8) * N + c] = make_float2(e2, e3);
            }
        }
    }
}

// ---------------------------------------------------------------------------
// Autocorrelation precompute (per batch, per 4-step block):
//   Q_j = sum(wx_j^2), W_ij = sum(wx_i*wx_j), i<j   (wx read as fp16)
// ---------------------------------------------------------------------------
__global__ __launch_bounds__(256)
void corr_kernel()
{
    const int blk = blockIdx.x;            // b*NBLK + q
    const int tid = threadIdx.x;
    const int w    = tid >> 5;
    const int lane = tid & 31;
    __shared__ float ws[10][8];

    const size_t rb = (size_t)blk * 4 * DI + tid * 4;
    float4 w0 = h2f4(*(const uint2*)&g_wx[rb]);
    float4 w1 = h2f4(*(const uint2*)&g_wx[rb + DI]);
    float4 w2 = h2f4(*(const uint2*)&g_wx[rb + 2 * DI]);
    float4 w3 = h2f4(*(const uint2*)&g_wx[rb + 3 * DI]);

    float p[10];
    p[0] = dot4(w0, w0); p[1] = dot4(w1, w1);
    p[2] = dot4(w2, w2); p[3] = dot4(w3, w3);
    p[4] = dot4(w0, w1); p[5] = dot4(w0, w2); p[6] = dot4(w0, w3);
    p[7] = dot4(w1, w2); p[8] = dot4(w1, w3); p[9] = dot4(w2, w3);

    #pragma unroll
    for (int i = 0; i < 10; i++) p[i] = warp_sum(p[i]);
    if (lane == 0) {
        #pragma unroll
        for (int i = 0; i < 10; i++) ws[i][w] = p[i];
    }
    __syncthreads();
    if (tid < 10) {
        float t = 0.f;
        #pragma unroll
        for (int k = 0; k < 8; k++) t += ws[tid][k];
        g_qw[(size_t)blk * 12 + tid] = t;
    }
}

// ---------------------------------------------------------------------------
// Lookahead-4 scan (R12): block loop unrolled x2 for static register-array
// indices; one __syncthreads per 4-step block. wx read as fp16 (uint2 regs).
// ---------------------------------------------------------------------------
__global__ __launch_bounds__(256)
void scan_kernel(const float* __restrict__ h0,
                 const float* __restrict__ log_alpha,
                 float* __restrict__ h_final)
{
    const int b    = blockIdx.x;
    const int tid  = threadIdx.x;
    const int w    = tid >> 5;
    const int lane = tid & 31;
    __shared__ __align__(16) float wsum[2][5][8];

    const float alpha = expf(log_alpha[0]);
    const float invD  = 1.0f / DI;

    float4 vv = *(const float4*)&h0[b * DI + tid * 4];
    float v0 = vv.x, v1 = vv.y, v2 = vv.z, v3 = vv.w;

    const size_t base   = (size_t)b * TT * DI + tid * 4;
    const size_t qwbase = (size_t)b * NBLK * 12;

    uint2  q[8];            // 2 blocks x 4 timesteps (fp16 packed)
    float4 qw[2][3];
    #pragma unroll
    for (int i = 0; i < 8; i++)
        q[i] = *(const uint2*)&g_wx[base + (size_t)i * DI];
    #pragma unroll
    for (int s = 0; s < 2; s++)
        #pragma unroll
        for (int i = 0; i < 3; i++)
            qw[s][i] = *(const float4*)&g_qw[qwbase + s * 12 + i * 4];

    for (int blk2 = 0; blk2 < NBLK; blk2 += 2) {
        #pragma unroll
        for (int par = 0; par < 2; par++) {          // compile-time par
            const int blk = blk2 + par;

            // snapshot current block (static indices), convert to fp32
            float4 w0 = h2f4(q[par * 4 + 0]), w1 = h2f4(q[par * 4 + 1]);
            float4 w2 = h2f4(q[par * 4 + 2]), w3 = h2f4(q[par * 4 + 3]);
            float4 qv0 = qw[par][0], qv1 = qw[par][1], qv2 = qw[par][2];

            // prefetch block blk+2 into this parity's slots
            if (blk + 2 < NBLK) {
                const size_t nb = base + (size_t)(blk + 2) * 4 * DI;
                q[par * 4 + 0] = *(const uint2*)&g_wx[nb];
                q[par * 4 + 1] = *(const uint2*)&g_wx[nb + DI];
                q[par * 4 + 2] = *(const uint2*)&g_wx[nb + 2 * DI];
                q[par * 4 + 3] = *(const uint2*)&g_wx[nb + 3 * DI];
                const size_t nq = qwbase + (size_t)(blk + 2) * 12;
                qw[par][0] = *(const float4*)&g_qw[nq];
                qw[par][1] = *(const float4*)&g_qw[nq + 4];
                qw[par][2] = *(const float4*)&g_qw[nq + 8];
            }

            // 5 per-thread partials
            float4 vf = make_float4(v0, v1, v2, v3);
            float pS = dot4(vf, vf);
            float p0 = dot4(vf, w0), p1 = dot4(vf, w1);
            float p2 = dot4(vf, w2), p3 = dot4(vf, w3);

            #pragma unroll
            for (int o = 16; o; o >>= 1) {
                pS += __shfl_xor_sync(0xffffffffu, pS, o);
                p0 += __shfl_xor_sync(0xffffffffu, p0, o);
                p1 += __shfl_xor_sync(0xffffffffu, p1, o);
                p2 += __shfl_xor_sync(0xffffffffu, p2, o);
                p3 += __shfl_xor_sync(0xffffffffu, p3, o);
            }
            if (lane == 0) {
                wsum[par][0][w] = pS;
                wsum[par][1][w] = p0; wsum[par][2][w] = p1;
                wsum[par][3][w] = p2; wsum[par][4][w] = p3;
            }
            __syncthreads();

            float S0, R0, R1, R2, R3;
            {
                float4 a0 = *(const float4*)&wsum[par][0][0];
                float4 c0 = *(const float4*)&wsum[par][0][4];
                S0 = ((a0.x + a0.y) + (a0.z + a0.w)) + ((c0.x + c0.y) + (c0.z + c0.w));
                float4 a1 = *(const float4*)&wsum[par][1][0];
                float4 c1_ = *(const float4*)&wsum[par][1][4];
                R0 = ((a1.x + a1.y) + (a1.z + a1.w)) + ((c1_.x + c1_.y) + (c1_.z + c1_.w));
                float4 a2 = *(const float4*)&wsum[par][2][0];
                float4 c2_ = *(const float4*)&wsum[par][2][4];
                R1 = ((a2.x + a2.y) + (a2.z + a2.w)) + ((c2_.x + c2_.y) + (c2_.z + c2_.w));
                float4 a3 = *(const float4*)&wsum[par][3][0];
                float4 c3_ = *(const float4*)&wsum[par][3][4];
                R2 = ((a3.x + a3.y) + (a3.z + a3.w)) + ((c3_.x + c3_.y) + (c3_.z + c3_.w));
                float4 a4 = *(const float4*)&wsum[par][4][0];
                float4 c4_ = *(const float4*)&wsum[par][4][4];
                R3 = ((a4.x + a4.y) + (a4.z + a4.w)) + ((c4_.x + c4_.y) + (c4_.z + c4_.w));
            }

            // scalar recursion (validated algebra)
            float S = S0, cval = 1.f, cc = 1.f, ic = 1.f;
            float k0, k1, k2, k3, c1, c2, c3, c4;
            {
                float P, m, r;
                k0 = alpha;
                P  = R0;
                S  = S + 2.f * k0 * P + k0 * k0 * qv0.x;
                m  = cc * S * invD + EPS;
                r  = rsqrtf(m);
                cval *= r; cc = cval * cval; ic *= m * r;
                c1 = cval;

                k1 = alpha * ic;
                P  = R1 + k0 * qv1.x;
                S  = S + 2.f * k1 * P + k1 * k1 * qv0.y;
                m  = cc * S * invD + EPS;
                r  = rsqrtf(m);
                cval *= r; cc = cval * cval; ic *= m * r;
                c2 = cval;

                k2 = alpha * ic;
                P  = R2 + k0 * qv1.y + k1 * qv1.w;
                S  = S + 2.f * k2 * P + k2 * k2 * qv0.z;
                m  = cc * S * invD + EPS;
                r  = rsqrtf(m);
                cval *= r; cc = cval * cval; ic *= m * r;
                c3 = cval;

                k3 = alpha * ic;
                P  = R3 + k0 * qv1.z + k1 * qv2.x + k2 * qv2.y;
                S  = S + 2.f * k3 * P + k3 * k3 * qv0.w;
                m  = cc * S * invD + EPS;
                r  = rsqrtf(m);
                cval *= r;
                c4 = cval;
            }

            // vector catch-up + outputs (straight-line)
            const size_t ob = base + (size_t)blk * 4 * DI;
            {
                float a0, a1, a2, a3;

                v0 = fmaf(k0, w0.x, v0); v1 = fmaf(k0, w0.y, v1);
                v2 = fmaf(k0, w0.z, v2); v3 = fmaf(k0, w0.w, v3);
                a0 = c1 * v0; a1 = c1 * v1; a2 = c1 * v2; a3 = c1 * v3;
                {
                    float o0 = __fdividef(a0 * a0, 1.0f + __expf(-a0));
                    float o1 = __fdividef(a1 * a1, 1.0f + __expf(-a1));
                    float o2 = __fdividef(a2 * a2, 1.0f + __expf(-a2));
                    float o3 = __fdividef(a3 * a3, 1.0f + __expf(-a3));
                    __half2 pa = __floats2half2_rn(o0, o1);
                    __half2 pb = __floats2half2_rn(o2, o3);
                    uint2 pk; pk.x = *(uint32_t*)&pa; pk.y = *(uint32_t*)&pb;
                    *(uint2*)&g_gate[ob] = pk;
                }

                v0 = fmaf(k1, w1.x, v0); v1 = fmaf(k1, w1.y, v1);
                v2 = fmaf(k1, w1.z, v2); v3 = fmaf(k1, w1.w, v3);
                a0 = c2 * v0; a1 = c2 * v1; a2 = c2 * v2; a3 = c2 * v3;
                {
                    float o0 = __fdividef(a0 * a0, 1.0f + __expf(-a0));
                    float o1 = __fdividef(a1 * a1, 1.0f + __expf(-a1));
                    float o2 = __fdividef(a2 * a2, 1.0f + __expf(-a2));
                    float o3 = __fdividef(a3 * a3, 1.0f + __expf(-a3));
                    __half2 pa = __floats2half2_rn(o0, o1);
                    __half2 pb = __floats2half2_rn(o2, o3);
                    uint2 pk; pk.x = *(uint32_t*)&pa; pk.y = *(uint32_t*)&pb;
                    *(uint2*)&g_gate[ob + DI] = pk;
                }

                v0 = fmaf(k2, w2.x, v0); v1 = fmaf(k2, w2.y, v1);
                v2 = fmaf(k2, w2.z, v2); v3 = fmaf(k2, w2.w, v3);
                a0 = c3 * v0; a1 = c3 * v1; a2 = c3 * v2; a3 = c3 * v3;
                {
                    float o0 = __fdividef(a0 * a0, 1.0f + __expf(-a0));
                    float o1 = __fdividef(a1 * a1, 1.0f + __expf(-a1));
                    float o2 = __fdividef(a2 * a2, 1.0f + __expf(-a2));
                    float o3 = __fdividef(a3 * a3, 1.0f + __expf(-a3));
                    __half2 pa = __floats2half2_rn(o0, o1);
                    __half2 pb = __floats2half2_rn(o2, o3);
                    uint2 pk; pk.x = *(uint32_t*)&pa; pk.y = *(uint32_t*)&pb;
                    *(uint2*)&g_gate[ob + 2 * DI] = pk;
                }

                v0 = fmaf(k3, w3.x, v0); v1 = fmaf(k3, w3.y, v1);
                v2 = fmaf(k3, w3.z, v2); v3 = fmaf(k3, w3.w, v3);
                a0 = c4 * v0; a1 = c4 * v1; a2 = c4 * v2; a3 = c4 * v3;
                {
                    float o0 = __fdividef(a0 * a0, 1.0f + __expf(-a0));
                    float o1 = __fdividef(a1 * a1, 1.0f + __expf(-a1));
                    float o2 = __fdividef(a2 * a2, 1.0f + __expf(-a2));
                    float o3 = __fdividef(a3 * a3, 1.0f + __expf(-a3));
                    __half2 pa = __floats2half2_rn(o0, o1);
                    __half2 pb = __floats2half2_rn(o2, o3);
                    uint2 pk; pk.x = *(uint32_t*)&pa; pk.y = *(uint32_t*)&pb;
                    *(uint2*)&g_gate[ob + 3 * DI] = pk;
                }

                v0 = a0; v1 = a1; v2 = a2; v3 = a3;   // fold c4 into v
            }
        }
    }

    if (h_final)
        *(float4*)&h_final[b * DI + tid * 4] = make_float4(v0, v1, v2, v3);
}

// ---------------------------------------------------------------------------
extern "C" void kernel_launch(void* const* d_in, const int* in_sizes, int n_in,
                              void* d_out, int out_size)
{
    const float* x         = (const float*)d_in[0];
    const float* h0        = (const float*)d_in[1];
    const float* W_in      = (const float*)d_in[2];
    const float* W_cell    = (const float*)d_in[3];
    const float* b_cell    = (const float*)d_in[4];
    const float* log_alpha = (const float*)d_in[5];
    const float* W_out     = (const float*)d_in[6];

    float* y = (float*)d_out;
    const size_t y_elems = (size_t)MM * DIM;
    float* h_final = ((size_t)out_size >= y_elems + (size_t)BAT * DI)
                         ? y + y_elems : nullptr;

    cudaFuncSetAttribute(gemm_hc<0>, cudaFuncAttributeMaxDynamicSharedMemorySize, SMEM_BYTES);
    cudaFuncSetAttribute(gemm_hc<1>, cudaFuncAttributeMaxDynamicSharedMemorySize, SMEM_BYTES);
    cudaFuncSetAttribute(gemm_hc<2>, cudaFuncAttributeMaxDynamicSharedMemorySize, SMEM_BYTES);

    __half *xa, *wi, *wc, *wo;
    cudaGetSymbolAddress((void**)&xa, g_xa);
    cudaGetSymbolAddress((void**)&wi, g_wi);
    cudaGetSymbolAddress((void**)&wc, g_wc);
    cudaGetSymbolAddress((void**)&wo, g_wo);

    // 0) convert mma operands to fp16
    {
        int n4x = (MM * DIM) / 4;
        to_half_kernel<<<(n4x + 255) / 256, 256>>>(x, xa, n4x);
        int n4w = (DI * DIM) / 4;
        to_half_kernel<<<(n4w + 255) / 256, 256>>>(W_in,   wi, n4w);
        to_half_kernel<<<(n4w + 255) / 256, 256>>>(W_cell, wc, n4w);
        to_half_kernel<<<(n4w + 255) / 256, 256>>>(W_out,  wo, n4w);
    }

    dim3 block(256);
    dim3 grid(DI / 128, MM / 128);

    // 1) xp = silu(x @ W_in^T)          -> g_xp (fp16)
    gemm_hc<0><<<grid, block, SMEM_BYTES>>>(nullptr, nullptr);
    // 2) Wx = xp @ W_cell^T + b_cell    -> g_wx (fp16)
    gemm_hc<1><<<grid, block, SMEM_BYTES>>>(b_cell, nullptr);
    // 2b) wx autocorrelations
    corr_kernel<<<BAT * NBLK, 256>>>();
    // 3) lookahead-4 scan                -> g_gate (fp16), h_final
    scan_kernel<<<BAT, 256>>>(h0, log_alpha, h_final);
    // 4) y = gate @ W_out^T             -> d_out
    gemm_hc<2><<<dim3(DIM / 128, MM / 128), block, SMEM_BYTES>>>(nullptr, y);
}